// round 16
// baseline (speedup 1.0000x reference)
#include <cuda_runtime.h>
#include <math.h>
#include <stdint.h>

#define NB 16
#define ND 1024
#define NL 512
#define NT 2048

// ---------------------------------------------------------------------------
// Scratch
// ---------------------------------------------------------------------------
__device__ uint32_t g_X1h[(size_t)NB * NT * ND / 2];  // input1^T hi [b,t,d]
__device__ uint32_t g_X1l[(size_t)NB * NT * ND / 2];
__device__ uint32_t g_X2h[(size_t)NB * NT * ND / 2];  // input2^T hi [b,t,d]
__device__ uint32_t g_X2l[(size_t)NB * NT * ND / 2];
__device__ uint32_t g_TWh[(size_t)NL * ND / 2];       // theta_w hi/lo [l,d]
__device__ uint32_t g_TWl[(size_t)NL * ND / 2];
__device__ uint32_t g_PWh[(size_t)NL * ND / 2];
__device__ uint32_t g_PWl[(size_t)NL * ND / 2];
__device__ uint32_t g_THh[(size_t)NB * NT * NL / 2];  // theta proj hi/lo [b,t,l]
__device__ uint32_t g_THl[(size_t)NB * NT * NL / 2];
__device__ uint32_t g_PHh[(size_t)NB * NT * NL / 2];
__device__ uint32_t g_PHl[(size_t)NB * NT * NL / 2];

__device__ float g_GX[(size_t)NB * NT * NL];   // g proj  [b,s,l] fp32
__device__ float g_TX[(size_t)NB * NT * NL];   // t_x     [b,t,l]
__device__ float g_H [(size_t)NB * NT * NL];   // LN+ReLU [b,t,l]
__device__ float g_S [(size_t)NB * NT * NT];   // scores/p [b,t,s]
__device__ float g_G2[(size_t)NT * NL];        // gamma^T [t,l]
__device__ float g_B2[(size_t)NT * NL];        // beta^T  [t,l]
__device__ float g_part[NB * 64 * 2];

// Stage geometry (R9 config: all GEMMs CTA 128x128, 2 CTAs/SM, 3 stages).
static constexpr int TILE_B_OFF = 18432;
static constexpr int STAGE_BYTES = 36864;
static constexpr int SMEMB_TF = 3 * STAGE_BYTES;   // 110592
static constexpr int BF_TILE = 8192;               // 128 * 64
static constexpr int BF_STAGE = 4 * BF_TILE;       // 32768
static constexpr int SMEMB_BF = 3 * BF_STAGE;      // 98304

// ---------------------------------------------------------------------------
// PTX helpers
// ---------------------------------------------------------------------------
__device__ __forceinline__ uint32_t f2tf(float f) {
    uint32_t r;
    asm("cvt.rna.tf32.f32 %0, %1;" : "=r"(r) : "f"(f));
    return r;
}

__device__ __forceinline__ void mma8(float* c, const uint32_t* a, const uint32_t* b) {
    asm volatile(
        "mma.sync.aligned.m16n8k8.row.col.f32.tf32.tf32.f32 "
        "{%0,%1,%2,%3}, {%4,%5,%6,%7}, {%8,%9}, {%0,%1,%2,%3};"
        : "+f"(c[0]), "+f"(c[1]), "+f"(c[2]), "+f"(c[3])
        : "r"(a[0]), "r"(a[1]), "r"(a[2]), "r"(a[3]), "r"(b[0]), "r"(b[1]));
}

__device__ __forceinline__ void mma16(float* c, const uint32_t* a, const uint32_t* b) {
    asm volatile(
        "mma.sync.aligned.m16n8k16.row.col.f32.bf16.bf16.f32 "
        "{%0,%1,%2,%3}, {%4,%5,%6,%7}, {%8,%9}, {%0,%1,%2,%3};"
        : "+f"(c[0]), "+f"(c[1]), "+f"(c[2]), "+f"(c[3])
        : "r"(a[0]), "r"(a[1]), "r"(a[2]), "r"(a[3]), "r"(b[0]), "r"(b[1]));
}

// Split (f0, f1) into packed bf16x2 hi + lo; f0 in low half.
__device__ __forceinline__ void bfsplit2(float f0, float f1, uint32_t& hi, uint32_t& lo) {
    asm("cvt.rn.bf16x2.f32 %0, %1, %2;" : "=r"(hi) : "f"(f1), "f"(f0));
    float h0 = __uint_as_float(hi << 16);
    float h1 = __uint_as_float(hi & 0xffff0000u);
    float l0 = f0 - h0, l1 = f1 - h1;
    asm("cvt.rn.bf16x2.f32 %0, %1, %2;" : "=r"(lo) : "f"(l1), "f"(l0));
}

__device__ __forceinline__ void cp16(uint32_t d, const void* s) {
    asm volatile("cp.async.cg.shared.global [%0], [%1], 16;" :: "r"(d), "l"(s));
}
__device__ __forceinline__ void cp_commit() {
    asm volatile("cp.async.commit_group;");
}
__device__ __forceinline__ void cp_wait1() {
    asm volatile("cp.async.wait_group 1;");
}

// Swizzled word index within a bf16 tile.
__device__ __forceinline__ int bfidx(int r, int c, int t) {
    return r * 16 + (((c) ^ ((r >> 1) & 3)) << 2) + t;
}

// ---------------------------------------------------------------------------
// Staging
// ---------------------------------------------------------------------------
// fp32 mode0: 128 rows x 32 floats -> rows padded to 144 B
__device__ __forceinline__ void stage_m0(uint32_t dst, const float* src, int stride) {
    const int tid = threadIdx.x;
    #pragma unroll
    for (int i = 0; i < 4; i++) {
        int id = tid + i * 256;
        int r = id >> 3, c = id & 7;
        cp16(dst + r * 144 + c * 16, src + (size_t)r * stride + c * 4);
    }
}
// fp32 mode1: 32 rows x 128 floats -> rows padded to 528 B
__device__ __forceinline__ void stage_m1(uint32_t dst, const float* src, int stride) {
    const int tid = threadIdx.x;
    #pragma unroll
    for (int i = 0; i < 4; i++) {
        int id = tid + i * 256;
        int r = id >> 5, c = id & 31;
        cp16(dst + r * 528 + c * 16, src + (size_t)r * stride + c * 4);
    }
}
// bf16 tile: 128 rows x 16 words (64B), XOR-swizzled 16B chunks
__device__ __forceinline__ void stage_bf(uint32_t dst, const uint32_t* src, int strideW) {
    const int tid = threadIdx.x;
    #pragma unroll
    for (int i = 0; i < 2; i++) {
        int id = tid + i * 256;
        int r = id >> 2, c = id & 3;
        uint32_t off = (uint32_t)(r * 16 + ((c ^ ((r >> 1) & 3)) << 2)) * 4;
        cp16(dst + off, src + (size_t)r * strideW + c * 4);
    }
}

// ---------------------------------------------------------------------------
// Pure-bf16x3 pipelined GEMM: 128x128 block, 8 warps (32m x 64n warp tile),
// K chunks of 32, 3-stage pipeline, ONE barrier per chunk.
// ---------------------------------------------------------------------------
template<class StageF>
__device__ __forceinline__ void gemm_bf3(int KC, StageF stage, float (*acc)[8][4])
{
    extern __shared__ char dsm[];
    const uint32_t sb = (uint32_t)__cvta_generic_to_shared(dsm);
    const int tid  = threadIdx.x;
    const int lane = tid & 31;
    const int m_off = ((tid >> 5) & 3) * 32;
    const int n_off = (tid >> 7) * 64;
    const int gid = lane >> 2, tig = lane & 3;

    #pragma unroll
    for (int i = 0; i < 2; i++)
        #pragma unroll
        for (int j = 0; j < 8; j++)
            #pragma unroll
            for (int k = 0; k < 4; k++) acc[i][j][k] = 0.f;

    stage(0, sb);
    cp_commit();
    stage(1, sb + BF_STAGE);
    cp_commit();

    for (int kc = 0; kc < KC; kc++) {
        cp_wait1();
        __syncthreads();
        if (kc + 2 < KC)
            stage(kc + 2, sb + ((kc + 2) % 3) * BF_STAGE);
        cp_commit();

        const int s = kc % 3;
        const uint32_t* Ah = (const uint32_t*)(dsm + s * BF_STAGE);
        const uint32_t* Al = (const uint32_t*)(dsm + s * BF_STAGE + BF_TILE);
        const uint32_t* Bh = (const uint32_t*)(dsm + s * BF_STAGE + 2 * BF_TILE);
        const uint32_t* Bl = (const uint32_t*)(dsm + s * BF_STAGE + 3 * BF_TILE);

        #pragma unroll
        for (int kh = 0; kh < 2; kh++) {
            uint32_t ah[2][4], al[2][4];
            #pragma unroll
            for (int mt = 0; mt < 2; mt++) {
                const int r0 = m_off + mt * 16 + gid;
                ah[mt][0] = Ah[bfidx(r0,     2*kh,     tig)];
                ah[mt][1] = Ah[bfidx(r0 + 8, 2*kh,     tig)];
                ah[mt][2] = Ah[bfidx(r0,     2*kh + 1, tig)];
                ah[mt][3] = Ah[bfidx(r0 + 8, 2*kh + 1, tig)];
                al[mt][0] = Al[bfidx(r0,     2*kh,     tig)];
                al[mt][1] = Al[bfidx(r0 + 8, 2*kh,     tig)];
                al[mt][2] = Al[bfidx(r0,     2*kh + 1, tig)];
                al[mt][3] = Al[bfidx(r0 + 8, 2*kh + 1, tig)];
            }
            #pragma unroll
            for (int nt = 0; nt < 8; nt++) {
                const int n = n_off + nt * 8 + gid;
                uint32_t bh[2], bl[2];
                bh[0] = Bh[bfidx(n, 2*kh,     tig)];
                bh[1] = Bh[bfidx(n, 2*kh + 1, tig)];
                bl[0] = Bl[bfidx(n, 2*kh,     tig)];
                bl[1] = Bl[bfidx(n, 2*kh + 1, tig)];
                #pragma unroll
                for (int mt = 0; mt < 2; mt++) {
                    mma16(acc[mt][nt], al[mt], bh);
                    mma16(acc[mt][nt], ah[mt], bl);
                    mma16(acc[mt][nt], ah[mt], bh);
                }
            }
        }
    }
    __syncthreads();
}

// ---------------------------------------------------------------------------
// tf32 1x pipelined GEMM (3 stages, ONE barrier per chunk).
//   A element (r,k): AM0: sA[r*36+k]  AM1: sA[k*132+r]
//   B element (k,n): BM0: sB[n*36+k]  BM1: sB[k*132+n]
// ---------------------------------------------------------------------------
template<int AM, int BM, class StageF>
__device__ __forceinline__ void gemm_tf(int KC, StageF stage, float (*acc)[8][4])
{
    extern __shared__ char dsm[];
    const uint32_t sb = (uint32_t)__cvta_generic_to_shared(dsm);
    const int tid  = threadIdx.x;
    const int lane = tid & 31;
    const int m_off = ((tid >> 5) & 3) * 32;
    const int n_off = (tid >> 7) * 64;
    const int gid = lane >> 2, tig = lane & 3;

    #pragma unroll
    for (int i = 0; i < 2; i++)
        #pragma unroll
        for (int j = 0; j < 8; j++)
            #pragma unroll
            for (int k = 0; k < 4; k++) acc[i][j][k] = 0.f;

    stage(0, sb, sb + TILE_B_OFF);
    cp_commit();
    stage(1, sb + STAGE_BYTES, sb + STAGE_BYTES + TILE_B_OFF);
    cp_commit();

    for (int kc = 0; kc < KC; kc++) {
        cp_wait1();
        __syncthreads();
        if (kc + 2 < KC) {
            const uint32_t nb = sb + ((kc + 2) % 3) * STAGE_BYTES;
            stage(kc + 2, nb, nb + TILE_B_OFF);
        }
        cp_commit();

        const int s = kc % 3;
        const float* sA = (const float*)(dsm + s * STAGE_BYTES);
        const float* sB = (const float*)(dsm + s * STAGE_BYTES + TILE_B_OFF);

        #pragma unroll
        for (int k8 = 0; k8 < 4; k8++) {
            const int kb = k8 * 8;
            uint32_t a[2][4];
            #pragma unroll
            for (int mt = 0; mt < 2; mt++) {
                const int r0 = m_off + mt * 16 + gid;
                if (AM == 0) {
                    a[mt][0] = f2tf(sA[r0 * 36 + kb + tig]);
                    a[mt][1] = f2tf(sA[(r0 + 8) * 36 + kb + tig]);
                    a[mt][2] = f2tf(sA[r0 * 36 + kb + tig + 4]);
                    a[mt][3] = f2tf(sA[(r0 + 8) * 36 + kb + tig + 4]);
                } else {
                    a[mt][0] = f2tf(sA[(kb + tig) * 132 + r0]);
                    a[mt][1] = f2tf(sA[(kb + tig) * 132 + r0 + 8]);
                    a[mt][2] = f2tf(sA[(kb + tig + 4) * 132 + r0]);
                    a[mt][3] = f2tf(sA[(kb + tig + 4) * 132 + r0 + 8]);
                }
            }
            #pragma unroll
            for (int nt = 0; nt < 8; nt++) {
                const int n = n_off + nt * 8 + gid;
                uint32_t bb[2];
                if (BM == 0) {
                    bb[0] = f2tf(sB[n * 36 + kb + tig]);
                    bb[1] = f2tf(sB[n * 36 + kb + tig + 4]);
                } else {
                    bb[0] = f2tf(sB[(kb + tig) * 132 + n]);
                    bb[1] = f2tf(sB[(kb + tig + 4) * 132 + n]);
                }
                #pragma unroll
                for (int mt = 0; mt < 2; mt++)
                    mma8(acc[mt][nt], a[mt], bb);
            }
        }
    }
    __syncthreads();
}

// ---------------------------------------------------------------------------
// Pre-split kernels (merged: index selects tensor)
// ---------------------------------------------------------------------------
// input [b][ND][NT] fp32 -> hi/lo bf16 words [b][NT][ND/2] (transposed)
// Grid (NT/32, ND/32, 2*NB): z>>4 = which input, z&15 = batch.
__global__ __launch_bounds__(256) void k_split_tr(const float* __restrict__ srcA,
                                                  uint32_t* __restrict__ hiA,
                                                  uint32_t* __restrict__ loA,
                                                  const float* __restrict__ srcB,
                                                  uint32_t* __restrict__ hiB,
                                                  uint32_t* __restrict__ loB)
{
    __shared__ float tile[32][33];
    const int which = blockIdx.z >> 4;
    const int b  = blockIdx.z & 15;
    const float* src = which ? srcB : srcA;
    uint32_t* hi = which ? hiB : hiA;
    uint32_t* lo = which ? loB : loA;
    const int x0 = blockIdx.x * 32;   // t
    const int y0 = blockIdx.y * 32;   // d
    const int tid = threadIdx.x;
    const int li = tid & 31, lj = tid >> 5;
    #pragma unroll
    for (int j = lj; j < 32; j += 8)
        tile[j][li] = src[(size_t)b * ND * NT + (size_t)(y0 + j) * NT + x0 + li];
    __syncthreads();
    #pragma unroll
    for (int i = 0; i < 2; i++) {
        int id = tid + i * 256;
        int tt = id >> 4, w = id & 15;
        float e = tile[2 * w][tt], o = tile[2 * w + 1][tt];
        uint32_t h, l;
        bfsplit2(e, o, h, l);
        size_t off = ((size_t)b * NT + x0 + tt) * (ND / 2) + y0 / 2 + w;
        hi[off] = h;
        lo[off] = l;
    }
}

// weights [NL][ND] fp32 -> hi/lo bf16 words; grid.x doubled, upper half = phi.
__global__ __launch_bounds__(256) void k_split_w(const float* __restrict__ srcA,
                                                 uint32_t* __restrict__ hiA,
                                                 uint32_t* __restrict__ loA,
                                                 const float* __restrict__ srcB,
                                                 uint32_t* __restrict__ hiB,
                                                 uint32_t* __restrict__ loB)
{
    const int half = NL * ND / 512;   // blocks per weight tensor
    const int which = blockIdx.x >= half;
    const float* src = which ? srcB : srcA;
    uint32_t* hi = which ? hiB : hiA;
    uint32_t* lo = which ? loB : loA;
    const size_t w = (size_t)(blockIdx.x - (which ? half : 0)) * 256 + threadIdx.x;
    float2 v = ((const float2*)src)[w];
    uint32_t h, l;
    bfsplit2(v.x, v.y, h, l);
    hi[w] = h;
    lo[w] = l;
}

// gamma/beta transpose merged: grid z=2 selects tensor. src [NL,NT] -> dst [NT,NL]
__global__ void k_transpose(const float* __restrict__ srcA, float* __restrict__ dstA,
                            const float* __restrict__ srcB, float* __restrict__ dstB)
{
    __shared__ float tile[32][33];
    const float* src = blockIdx.z ? srcB : srcA;
    float* dst = blockIdx.z ? dstB : dstA;
    const int x  = blockIdx.x * 32 + threadIdx.x;
    const int y0 = blockIdx.y * 32;
    #pragma unroll
    for (int j = threadIdx.y; j < 32; j += 8)
        tile[j][threadIdx.x] = src[(size_t)(y0 + j) * NT + x];
    __syncthreads();
    const int xo  = blockIdx.y * 32 + threadIdx.x;
    const int yo0 = blockIdx.x * 32;
    #pragma unroll
    for (int j = threadIdx.y; j < 32; j += 8)
        dst[(size_t)(yo0 + j) * NL + xo] = tile[threadIdx.x][j];
}

// ---------------------------------------------------------------------------
// GEMM kernels (all CTA 128x128, R9 config)
// ---------------------------------------------------------------------------

// Merged theta+phi projection (bf16x3): C[b,t,l] = sum_d XT[b,t,d]*W[l,d]+bias[l]
// Grid: (NL/128, NT/128, 2*NB). z>>4 selects (theta|phi) operand set; z&15 = b.
__global__ __launch_bounds__(256, 2)
void k_proj_bf(const uint32_t* __restrict__ TWh_, const uint32_t* __restrict__ TWl_,
               const uint32_t* __restrict__ X2h_, const uint32_t* __restrict__ X2l_,
               const float* __restrict__ tb_,
               uint32_t* __restrict__ THh_, uint32_t* __restrict__ THl_,
               const uint32_t* __restrict__ PWh_, const uint32_t* __restrict__ PWl_,
               const uint32_t* __restrict__ X1h_, const uint32_t* __restrict__ X1l_,
               const float* __restrict__ pb_,
               uint32_t* __restrict__ PHh_, uint32_t* __restrict__ PHl_)
{
    const int which = blockIdx.z >> 4;
    const int b  = blockIdx.z & 15;
    const uint32_t* Wh = which ? PWh_ : TWh_;
    const uint32_t* Wl = which ? PWl_ : TWl_;
    const uint32_t* Xh = which ? X1h_ : X2h_;
    const uint32_t* Xl = which ? X1l_ : X2l_;
    const float* bias  = which ? pb_ : tb_;
    uint32_t* Ch = which ? PHh_ : THh_;
    uint32_t* Cl = which ? PHl_ : THl_;

    const int n0 = blockIdx.x * 128;   // l
    const int m0 = blockIdx.y * 128;   // t
    const uint32_t* XhB = Xh + ((size_t)b * NT + m0) * (ND / 2);
    const uint32_t* XlB = Xl + ((size_t)b * NT + m0) * (ND / 2);
    const uint32_t* WhB = Wh + (size_t)n0 * (ND / 2);
    const uint32_t* WlB = Wl + (size_t)n0 * (ND / 2);

    float acc[2][8][4];
    auto stage = [&](int kc, uint32_t base) {
        stage_bf(base,               XhB + kc * 16, ND / 2);
        stage_bf(base + BF_TILE,     XlB + kc * 16, ND / 2);
        stage_bf(base + 2 * BF_TILE, WhB + kc * 16, ND / 2);
        stage_bf(base + 3 * BF_TILE, WlB + kc * 16, ND / 2);
    };
    gemm_bf3(ND / 32, stage, acc);

    const int tid = threadIdx.x, lane = tid & 31;
    const int m_off = ((tid >> 5) & 3) * 32, n_off = (tid >> 7) * 64;
    const int gid = lane >> 2, tig = lane & 3;
    #pragma unroll
    for (int mt = 0; mt < 2; mt++) {
        const int r0 = m0 + m_off + mt * 16 + gid;
        #pragma unroll
        for (int nt = 0; nt < 8; nt++) {
            const int col = n0 + n_off + nt * 8 + tig * 2;
            float2 bi = *(const float2*)(bias + col);
            uint32_t h, l;
            size_t o0 = ((size_t)b * NT + r0) * (NL / 2) + col / 2;
            bfsplit2(acc[mt][nt][0] + bi.x, acc[mt][nt][1] + bi.y, h, l);
            Ch[o0] = h; Cl[o0] = l;
            size_t o1 = ((size_t)b * NT + r0 + 8) * (NL / 2) + col / 2;
            bfsplit2(acc[mt][nt][2] + bi.x, acc[mt][nt][3] + bi.y, h, l);
            Ch[o1] = h; Cl[o1] = l;
        }
    }
}

// Scores (bf16x3): S[b,t,s] = sum_l TH[b,t,l] * PH[b,s,l]. Grid (16,16,NB)
__global__ __launch_bounds__(256, 2)
void k_scores_bf(const uint32_t* __restrict__ Ah, const uint32_t* __restrict__ Al,
                 const uint32_t* __restrict__ Bh, const uint32_t* __restrict__ Bl,
                 float* __restrict__ S)
{
    const int b  = blockIdx.z;
    const int n0 = blockIdx.x * 128;   // s
    const int m0 = blockIdx.y * 128;   // t
    const uint32_t* AhB = Ah + ((size_t)b * NT + m0) * (NL / 2);
    const uint32_t* AlB = Al + ((size_t)b * NT + m0) * (NL / 2);
    const uint32_t* BhB = Bh + ((size_t)b * NT + n0) * (NL / 2);
    const uint32_t* BlB = Bl + ((size_t)b * NT + n0) * (NL / 2);

    float acc[2][8][4];
    auto stage = [&](int kc, uint32_t base) {
        stage_bf(base,               AhB + kc * 16, NL / 2);
        stage_bf(base + BF_TILE,     AlB + kc * 16, NL / 2);
        stage_bf(base + 2 * BF_TILE, BhB + kc * 16, NL / 2);
        stage_bf(base + 3 * BF_TILE, BlB + kc * 16, NL / 2);
    };
    gemm_bf3(NL / 32, stage, acc);

    const int tid = threadIdx.x, lane = tid & 31;
    const int m_off = ((tid >> 5) & 3) * 32, n_off = (tid >> 7) * 64;
    const int gid = lane >> 2, tig = lane & 3;
    float* Sb = S + (size_t)b * NT * NT;
    #pragma unroll
    for (int mt = 0; mt < 2; mt++) {
        const int r0 = m0 + m_off + mt * 16 + gid;
        #pragma unroll
        for (int nt = 0; nt < 8; nt++) {
            const int col = n0 + n_off + nt * 8 + tig * 2;
            *(float2*)(Sb + (size_t)r0 * NT + col) =
                make_float2(acc[mt][nt][0], acc[mt][nt][1]);
            *(float2*)(Sb + (size_t)(r0 + 8) * NT + col) =
                make_float2(acc[mt][nt][2], acc[mt][nt][3]);
        }
    }
}

// g-projection (tf32 1x): C[b,t,l] = sum_d X[b,d,t] * W[l,d] + bias[l]
// A = X (M=t, mode1), B = W (mode0). Grid: (NL/128, NT/128, NB)
__global__ __launch_bounds__(256, 2)
void k_proj_tf(const float* __restrict__ W, const float* __restrict__ X,
               const float* __restrict__ bias, float* __restrict__ C)
{
    const int b  = blockIdx.z;
    const int n0 = blockIdx.x * 128;   // l
    const int m0 = blockIdx.y * 128;   // t
    const float* Xb = X + (size_t)b * ND * NT;

    float acc[2][8][4];
    auto stage = [&](int kc, uint32_t bA, uint32_t bB) {
        stage_m1(bA, Xb + (size_t)(kc * 32) * NT + m0, NT);
        stage_m0(bB, W  + (size_t)n0 * ND + kc * 32, ND);
    };
    gemm_tf<1, 0>(ND / 32, stage, acc);

    const int tid = threadIdx.x, lane = tid & 31;
    const int m_off = ((tid >> 5) & 3) * 32, n_off = (tid >> 7) * 64;
    const int gid = lane >> 2, tig = lane & 3;
    float* Cb = C + (size_t)b * NT * NL;
    #pragma unroll
    for (int mt = 0; mt < 2; mt++) {
        const int r0 = m0 + m_off + mt * 16 + gid;
        #pragma unroll
        for (int nt = 0; nt < 8; nt++) {
            const int col = n0 + n_off + nt * 8 + tig * 2;
            float2 bi = *(const float2*)(bias + col);
            *(float2*)(Cb + (size_t)r0 * NL + col) =
                make_float2(acc[mt][nt][0] + bi.x, acc[mt][nt][1] + bi.y);
            *(float2*)(Cb + (size_t)(r0 + 8) * NL + col) =
                make_float2(acc[mt][nt][2] + bi.x, acc[mt][nt][3] + bi.y);
        }
    }
}

// t_x (tf32 1x): TX[b,t,l] = sum_s P[b,t,s] * GX[b,s,l].
// Emits per-CTA LN partials (deterministic). Grid (NL/128, NT/128, NB)
__global__ __launch_bounds__(256, 2)
void k_tx_tc(const float* __restrict__ P, const float* __restrict__ GX,
             float* __restrict__ TX)
{
    const int b  = blockIdx.z;
    const int n0 = blockIdx.x * 128;   // l
    const int m0 = blockIdx.y * 128;   // t
    const float* A  = P  + (size_t)b * NT * NT;
    const float* Bp = GX + (size_t)b * NT * NL;

    float acc[2][8][4];
    auto stage = [&](int kc, uint32_t bA, uint32_t bB) {
        stage_m0(bA, A  + (size_t)m0 * NT + kc * 32, NT);
        stage_m1(bB, Bp + (size_t)(kc * 32) * NL + n0, NL);
    };
    gemm_tf<0, 1>(NT / 32, stage, acc);

    const int tid = threadIdx.x, lane = tid & 31;
    const int m_off = ((tid >> 5) & 3) * 32, n_off = (tid >> 7) * 64;
    const int gid = lane >> 2, tig = lane & 3;
    float* Tb = TX + (size_t)b * NT * NL;
    float s = 0.f, q = 0.f;
    #pragma unroll
    for (int mt = 0; mt < 2; mt++) {
        const int r0 = m0 + m_off + mt * 16 + gid;
        #pragma unroll
        for (int nt = 0; nt < 8; nt++) {
            const int col = n0 + n_off + nt * 8 + tig * 2;
            float4 v = make_float4(acc[mt][nt][0], acc[mt][nt][1],
                                   acc[mt][nt][2], acc[mt][nt][3]);
            *(float2*)(Tb + (size_t)r0 * NL + col) = make_float2(v.x, v.y);
            *(float2*)(Tb + (size_t)(r0 + 8) * NL + col) = make_float2(v.z, v.w);
            s += v.x + v.y + v.z + v.w;
            q += v.x * v.x + v.y * v.y + v.z * v.z + v.w * v.w;
        }
    }
    // Deterministic per-CTA LN partials.
    extern __shared__ char dsm[];
    float* red = (float*)dsm;
    #pragma unroll
    for (int o = 16; o > 0; o >>= 1) {
        s += __shfl_xor_sync(0xffffffffu, s, o);
        q += __shfl_xor_sync(0xffffffffu, q, o);
    }
    __syncthreads();
    if (lane == 0) { red[tid >> 5] = s; red[8 + (tid >> 5)] = q; }
    __syncthreads();
    if (tid == 0) {
        float ts = 0.f, tq = 0.f;
        #pragma unroll
        for (int w = 0; w < 8; w++) { ts += red[w]; tq += red[8 + w]; }
        const int cta = blockIdx.y * 4 + blockIdx.x;   // 0..63 per batch
        g_part[(b * 64 + cta) * 2]     = ts;
        g_part[(b * 64 + cta) * 2 + 1] = tq;
    }
}

// Out (tf32 1x): Out[b,o,t] = sum_l OW[o,l] * H[b,t,l] + ob[o] + in2[b,o,t].
// Grid (NT/128, ND/128, NB)
__global__ __launch_bounds__(256, 2)
void k_out_tc(const float* __restrict__ OW, const float* __restrict__ H,
              const float* __restrict__ ob, const float* __restrict__ in2,
              float* __restrict__ Out)
{
    const int b  = blockIdx.z;
    const int n0 = blockIdx.x * 128;   // t
    const int m0 = blockIdx.y * 128;   // o
    const float* Hb = H + (size_t)b * NT * NL;

    float acc[2][8][4];
    auto stage = [&](int kc, uint32_t bA, uint32_t bB) {
        stage_m0(bA, OW + (size_t)m0 * NL + kc * 32, NL);
        stage_m0(bB, Hb + (size_t)n0 * NL + kc * 32, NL);
    };
    gemm_tf<0, 0>(NL / 32, stage, acc);

    const int tid = threadIdx.x, lane = tid & 31;
    const int m_off = ((tid >> 5) & 3) * 32, n_off = (tid >> 7) * 64;
    const int gid = lane >> 2, tig = lane & 3;
    #pragma unroll
    for (int mt = 0; mt < 2; mt++) {
        const int r0 = m0 + m_off + mt * 16 + gid;
        const float bi0 = ob[r0], bi1 = ob[r0 + 8];
        const size_t base0 = ((size_t)b * ND + r0) * NT;
        const size_t base1 = ((size_t)b * ND + r0 + 8) * NT;
        #pragma unroll
        for (int nt = 0; nt < 8; nt++) {
            const int col = n0 + n_off + nt * 8 + tig * 2;
            float2 q0 = *(const float2*)(in2 + base0 + col);
            float2 q1 = *(const float2*)(in2 + base1 + col);
            *(float2*)(Out + base0 + col) =
                make_float2(acc[mt][nt][0] + bi0 + q0.x, acc[mt][nt][1] + bi0 + q0.y);
            *(float2*)(Out + base1 + col) =
                make_float2(acc[mt][nt][2] + bi1 + q1.x, acc[mt][nt][3] + bi1 + q1.y);
        }
    }
}

// ---------------------------------------------------------------------------
// Elementwise / reductions
// ---------------------------------------------------------------------------
__device__ __forceinline__ float warpMax(float v) {
    #pragma unroll
    for (int o = 16; o > 0; o >>= 1) v = fmaxf(v, __shfl_xor_sync(0xffffffffu, v, o));
    return v;
}
__device__ __forceinline__ float warpSum(float v) {
    #pragma unroll
    for (int o = 16; o > 0; o >>= 1) v += __shfl_xor_sync(0xffffffffu, v, o);
    return v;
}

__global__ __launch_bounds__(256) void k_softmax(float* __restrict__ S)
{
    float* p = S + (size_t)blockIdx.x * NT;
    const int tid = threadIdx.x;
    float4 v0 = ((float4*)p)[tid];
    float4 v1 = ((float4*)p)[tid + 256];

    __shared__ float sm[8];
    float m = fmaxf(fmaxf(fmaxf(v0.x, v0.y), fmaxf(v0.z, v0.w)),
                    fmaxf(fmaxf(v1.x, v1.y), fmaxf(v1.z, v1.w)));
    m = warpMax(m);
    if ((tid & 31) == 0) sm[tid >> 5] = m;
    __syncthreads();
    if (tid < 32) {
        float t = (tid < 8) ? sm[tid] : -1e30f;
        t = warpMax(t);
        if (tid == 0) sm[0] = t;
    }
    __syncthreads();
    const float bm = sm[0];
    __syncthreads();

    v0.x = __expf(v0.x - bm); v0.y = __expf(v0.y - bm);
    v0.z = __expf(v0.z - bm); v0.w = __expf(v0.w - bm);
    v1.x = __expf(v1.x - bm); v1.y = __expf(v1.y - bm);
    v1.z = __expf(v1.z - bm); v1.w = __expf(v1.w - bm);
    float s = v0.x + v0.y + v0.z + v0.w + v1.x + v1.y + v1.z + v1.w;
    s = warpSum(s);
    if ((tid & 31) == 0) sm[tid >> 5] = s;
    __syncthreads();
    if (tid < 32) {
        float t = (tid < 8) ? sm[tid] : 0.f;
        t = warpSum(t);
        if (tid == 0) sm[0] = t;
    }
    __syncthreads();
    const float inv = 1.f / sm[0];
    v0.x *= inv; v0.y *= inv; v0.z *= inv; v0.w *= inv;
    v1.x *= inv; v1.y *= inv; v1.z *= inv; v1.w *= inv;
    ((float4*)p)[tid] = v0;
    ((float4*)p)[tid + 256] = v1;
}

// H = relu((TX - mu) * rstd * G2 + B2), all [b,t,l].
// Stats computed per-block from g_part with the SAME deterministic order the
// old k_finalize used (c = 0..63 sequential), so results are bit-identical.
__global__ __launch_bounds__(256) void k_ln(const float* __restrict__ TX,
                                            const float* __restrict__ G2,
                                            const float* __restrict__ B2,
                                            float* __restrict__ H)
{
    const int b = blockIdx.y;
    float s = 0.f, q = 0.f;
    #pragma unroll
    for (int c = 0; c < 64; c++) {
        s += g_part[(b * 64 + c) * 2];
        q += g_part[(b * 64 + c) * 2 + 1];
    }
    const float n = (float)NL * (float)NT;
    const float mu = s / n;
    const float rs = rsqrtf(q / n - mu * mu + 1e-5f);

    const size_t i = (size_t)blockIdx.x * 256 + threadIdx.x;
    float4 x  = ((const float4*)(TX + (size_t)b * NL * NT))[i];
    float4 g  = ((const float4*)G2)[i];
    float4 be = ((const float4*)B2)[i];
    float4 h;
    h.x = fmaxf((x.x - mu) * rs * g.x + be.x, 0.f);
    h.y = fmaxf((x.y - mu) * rs * g.y + be.y, 0.f);
    h.z = fmaxf((x.z - mu) * rs * g.z + be.z, 0.f);
    h.w = fmaxf((x.w - mu) * rs * g.w + be.w, 0.f);
    ((float4*)(H + (size_t)b * NL * NT))[i] = h;
}

// ---------------------------------------------------------------------------
// Launch
// ---------------------------------------------------------------------------
extern "C" void kernel_launch(void* const* d_in, const int* in_sizes, int n_in,
                              void* d_out, int out_size)
{
    const float* input1  = (const float*)d_in[0];
    const float* input2  = (const float*)d_in[1];
    const float* theta_w = (const float*)d_in[2];
    const float* theta_b = (const float*)d_in[3];
    const float* phi_w   = (const float*)d_in[4];
    const float* phi_b   = (const float*)d_in[5];
    const float* g_w     = (const float*)d_in[6];
    const float* g_b     = (const float*)d_in[7];
    const float* ln_g    = (const float*)d_in[8];
    const float* ln_b    = (const float*)d_in[9];
    const float* out_w   = (const float*)d_in[10];
    const float* out_b   = (const float*)d_in[11];
    float* out = (float*)d_out;

    uint32_t *X1h, *X1l, *X2h, *X2l, *TWh, *TWl, *PWh, *PWl;
    uint32_t *THh, *THl, *PHh, *PHl;
    float *GX, *TX, *H, *S, *G2, *B2;
    cudaGetSymbolAddress((void**)&X1h, g_X1h);
    cudaGetSymbolAddress((void**)&X1l, g_X1l);
    cudaGetSymbolAddress((void**)&X2h, g_X2h);
    cudaGetSymbolAddress((void**)&X2l, g_X2l);
    cudaGetSymbolAddress((void**)&TWh, g_TWh);
    cudaGetSymbolAddress((void**)&TWl, g_TWl);
    cudaGetSymbolAddress((void**)&PWh, g_PWh);
    cudaGetSymbolAddress((void**)&PWl, g_PWl);
    cudaGetSymbolAddress((void**)&THh, g_THh);
    cudaGetSymbolAddress((void**)&THl, g_THl);
    cudaGetSymbolAddress((void**)&PHh, g_PHh);
    cudaGetSymbolAddress((void**)&PHl, g_PHl);
    cudaGetSymbolAddress((void**)&GX, g_GX);
    cudaGetSymbolAddress((void**)&TX, g_TX);
    cudaGetSymbolAddress((void**)&H,  g_H);
    cudaGetSymbolAddress((void**)&S,  g_S);
    cudaGetSymbolAddress((void**)&G2, g_G2);
    cudaGetSymbolAddress((void**)&B2, g_B2);

    cudaFuncSetAttribute(k_proj_bf,   cudaFuncAttributeMaxDynamicSharedMemorySize, SMEMB_BF);
    cudaFuncSetAttribute(k_scores_bf, cudaFuncAttributeMaxDynamicSharedMemorySize, SMEMB_BF);
    cudaFuncSetAttribute(k_proj_tf,   cudaFuncAttributeMaxDynamicSharedMemorySize, SMEMB_TF);
    cudaFuncSetAttribute(k_tx_tc,     cudaFuncAttributeMaxDynamicSharedMemorySize, SMEMB_TF);
    cudaFuncSetAttribute(k_out_tc,    cudaFuncAttributeMaxDynamicSharedMemorySize, SMEMB_TF);

    dim3 blk(256);

    // Pre-splits (merged pairs) — 3 launches, so launch #6 is k_scores_bf
    dim3 gst(NT / 32, ND / 32, 2 * NB);
    k_split_tr<<<gst, blk>>>(input2, X2h, X2l, input1, X1h, X1l);
    k_split_w<<<2 * NL * ND / 512, blk>>>(theta_w, TWh, TWl, phi_w, PWh, PWl);
    dim3 gtr(NT / 32, NL / 32, 2);
    k_transpose<<<gtr, dim3(32, 8)>>>(ln_g, G2, ln_b, B2);

    // Projections: merged theta+phi (bf16x3), then g (tf32)
    dim3 gpbf(NL / 128, NT / 128, 2 * NB);
    k_proj_bf<<<gpbf, blk, SMEMB_BF>>>(TWh, TWl, X2h, X2l, theta_b, THh, THl,
                                       PWh, PWl, X1h, X1l, phi_b, PHh, PHl);
    dim3 gptf(NL / 128, NT / 128, NB);
    k_proj_tf<<<gptf, blk, SMEMB_TF>>>(g_w, input1, g_b, GX);

    // Scores + softmax
    dim3 gsc(NT / 128, NT / 128, NB);
    k_scores_bf<<<gsc, blk, SMEMB_BF>>>(THh, THl, PHh, PHl, S);
    k_softmax<<<NB * NT, 256>>>(S);

    // Attention apply (+ fused LN partials)
    dim3 gtx(NL / 128, NT / 128, NB);
    k_tx_tc<<<gtx, blk, SMEMB_TF>>>(S, GX, TX);

    // LayerNorm (stats folded in)
    k_ln<<<dim3(NL * NT / 1024, NB), 256>>>(TX, G2, B2, H);

    // Output GEMM
    dim3 gout(NT / 128, ND / 128, NB);
    k_out_tc<<<gout, blk, SMEMB_TF>>>(out_w, H, out_b, input2, out);
}

// round 17
// speedup vs baseline: 1.0346x; 1.0346x over previous
#include <cuda_runtime.h>
#include <math.h>
#include <stdint.h>

#define NB 16
#define ND 1024
#define NL 512
#define NT 2048

// ---------------------------------------------------------------------------
// Scratch
// ---------------------------------------------------------------------------
__device__ uint32_t g_X1h[(size_t)NB * NT * ND / 2];  // input1^T hi [b,t,d]
__device__ uint32_t g_X1l[(size_t)NB * NT * ND / 2];
__device__ uint32_t g_X2h[(size_t)NB * NT * ND / 2];  // input2^T hi [b,t,d]
__device__ uint32_t g_X2l[(size_t)NB * NT * ND / 2];
__device__ uint32_t g_TWh[(size_t)NL * ND / 2];       // theta_w hi/lo [l,d]
__device__ uint32_t g_TWl[(size_t)NL * ND / 2];
__device__ uint32_t g_PWh[(size_t)NL * ND / 2];
__device__ uint32_t g_PWl[(size_t)NL * ND / 2];
__device__ uint32_t g_THh[(size_t)NB * NT * NL / 2];  // theta proj hi/lo [b,t,l]
__device__ uint32_t g_THl[(size_t)NB * NT * NL / 2];
__device__ uint32_t g_PHh[(size_t)NB * NT * NL / 2];
__device__ uint32_t g_PHl[(size_t)NB * NT * NL / 2];

__device__ float g_GX[(size_t)NB * NT * NL];   // g proj  [b,s,l] fp32
__device__ float g_TX[(size_t)NB * NT * NL];   // t_x     [b,t,l]
__device__ float g_H [(size_t)NB * NT * NL];   // LN+ReLU [b,t,l]
__device__ float g_S [(size_t)NB * NT * NT];   // scores/p [b,t,s]
__device__ float g_G2[(size_t)NT * NL];        // gamma^T [t,l]
__device__ float g_B2[(size_t)NT * NL];        // beta^T  [t,l]
__device__ float g_part[NB * 64 * 2];
__device__ float g_stats[NB * 2];

// Stage geometry (R9 config: all GEMMs CTA 128x128, 2 CTAs/SM, 3 stages).
static constexpr int TILE_B_OFF = 18432;
static constexpr int STAGE_BYTES = 36864;
static constexpr int SMEMB_TF = 3 * STAGE_BYTES;   // 110592
static constexpr int BF_TILE = 8192;               // 128 * 64
static constexpr int BF_STAGE = 4 * BF_TILE;       // 32768
static constexpr int SMEMB_BF = 3 * BF_STAGE;      // 98304

// ---------------------------------------------------------------------------
// PTX helpers
// ---------------------------------------------------------------------------
__device__ __forceinline__ uint32_t f2tf(float f) {
    uint32_t r;
    asm("cvt.rna.tf32.f32 %0, %1;" : "=r"(r) : "f"(f));
    return r;
}

__device__ __forceinline__ void mma8(float* c, const uint32_t* a, const uint32_t* b) {
    asm volatile(
        "mma.sync.aligned.m16n8k8.row.col.f32.tf32.tf32.f32 "
        "{%0,%1,%2,%3}, {%4,%5,%6,%7}, {%8,%9}, {%0,%1,%2,%3};"
        : "+f"(c[0]), "+f"(c[1]), "+f"(c[2]), "+f"(c[3])
        : "r"(a[0]), "r"(a[1]), "r"(a[2]), "r"(a[3]), "r"(b[0]), "r"(b[1]));
}

__device__ __forceinline__ void mma16(float* c, const uint32_t* a, const uint32_t* b) {
    asm volatile(
        "mma.sync.aligned.m16n8k16.row.col.f32.bf16.bf16.f32 "
        "{%0,%1,%2,%3}, {%4,%5,%6,%7}, {%8,%9}, {%0,%1,%2,%3};"
        : "+f"(c[0]), "+f"(c[1]), "+f"(c[2]), "+f"(c[3])
        : "r"(a[0]), "r"(a[1]), "r"(a[2]), "r"(a[3]), "r"(b[0]), "r"(b[1]));
}

// ldmatrix: 4x / 2x 8x8 b16 tiles. Per-thread row addresses.
__device__ __forceinline__ void ldsm_x4(uint32_t* r, uint32_t addr) {
    asm volatile(
        "ldmatrix.sync.aligned.m8n8.x4.shared.b16 {%0,%1,%2,%3}, [%4];"
        : "=r"(r[0]), "=r"(r[1]), "=r"(r[2]), "=r"(r[3]) : "r"(addr));
}
__device__ __forceinline__ void ldsm_x2(uint32_t* r, uint32_t addr) {
    asm volatile(
        "ldmatrix.sync.aligned.m8n8.x2.shared.b16 {%0,%1}, [%2];"
        : "=r"(r[0]), "=r"(r[1]) : "r"(addr));
}

// Split (f0, f1) into packed bf16x2 hi + lo; f0 in low half.
__device__ __forceinline__ void bfsplit2(float f0, float f1, uint32_t& hi, uint32_t& lo) {
    asm("cvt.rn.bf16x2.f32 %0, %1, %2;" : "=r"(hi) : "f"(f1), "f"(f0));
    float h0 = __uint_as_float(hi << 16);
    float h1 = __uint_as_float(hi & 0xffff0000u);
    float l0 = f0 - h0, l1 = f1 - h1;
    asm("cvt.rn.bf16x2.f32 %0, %1, %2;" : "=r"(lo) : "f"(l1), "f"(l0));
}

__device__ __forceinline__ void cp16(uint32_t d, const void* s) {
    asm volatile("cp.async.cg.shared.global [%0], [%1], 16;" :: "r"(d), "l"(s));
}
__device__ __forceinline__ void cp_commit() {
    asm volatile("cp.async.commit_group;");
}
__device__ __forceinline__ void cp_wait1() {
    asm volatile("cp.async.wait_group 1;");
}

// ---------------------------------------------------------------------------
// Staging
// ---------------------------------------------------------------------------
// fp32 mode0: 128 rows x 32 floats -> rows padded to 144 B
__device__ __forceinline__ void stage_m0(uint32_t dst, const float* src, int stride) {
    const int tid = threadIdx.x;
    #pragma unroll
    for (int i = 0; i < 4; i++) {
        int id = tid + i * 256;
        int r = id >> 3, c = id & 7;
        cp16(dst + r * 144 + c * 16, src + (size_t)r * stride + c * 4);
    }
}
// fp32 mode1: 32 rows x 128 floats -> rows padded to 528 B
__device__ __forceinline__ void stage_m1(uint32_t dst, const float* src, int stride) {
    const int tid = threadIdx.x;
    #pragma unroll
    for (int i = 0; i < 4; i++) {
        int id = tid + i * 256;
        int r = id >> 5, c = id & 31;
        cp16(dst + r * 528 + c * 16, src + (size_t)r * stride + c * 4);
    }
}
// bf16 tile: 128 rows x 16 words (64B), XOR-swizzled 16B chunks
__device__ __forceinline__ void stage_bf(uint32_t dst, const uint32_t* src, int strideW) {
    const int tid = threadIdx.x;
    #pragma unroll
    for (int i = 0; i < 2; i++) {
        int id = tid + i * 256;
        int r = id >> 2, c = id & 3;
        uint32_t off = (uint32_t)(r * 16 + ((c ^ ((r >> 1) & 3)) << 2)) * 4;
        cp16(dst + off, src + (size_t)r * strideW + c * 4);
    }
}

// ---------------------------------------------------------------------------
// Pure-bf16x3 pipelined GEMM: 128x128 block, 8 warps (32m x 64n warp tile),
// K chunks of 32, 3-stage pipeline, ONE barrier per chunk.
// Fragments loaded via ldmatrix (swizzle absorbed into per-thread row addrs).
// ---------------------------------------------------------------------------
template<class StageF>
__device__ __forceinline__ void gemm_bf3(int KC, StageF stage, float (*acc)[8][4])
{
    extern __shared__ char dsm[];
    const uint32_t sb = (uint32_t)__cvta_generic_to_shared(dsm);
    const int tid  = threadIdx.x;
    const int lane = tid & 31;
    const int m_off = ((tid >> 5) & 3) * 32;
    const int n_off = (tid >> 7) * 64;

    // ldmatrix per-thread relative offsets (within a tile), for kh = 0,1.
    // A (x4): row = m_off + mt*16 + (lane&15); chunk = 2kh + (lane>>4).
    // B (x2): row = n_off + nt*8 + (lane&7) [lanes 16-31 mirror 0-15];
    //         chunk = 2kh + ((lane&15)>>3).
    const int ar = lane & 15;
    const int ac = lane >> 4;
    const int sw_a = (ar >> 1) & 3;
    const int br = lane & 7;
    const int bc = (lane & 15) >> 3;
    const int sw_b = (br >> 1) & 3;
    uint32_t aRel[2], bRel[2];
    #pragma unroll
    for (int kh = 0; kh < 2; kh++) {
        aRel[kh] = (uint32_t)(ar * 64 + (((2 * kh + ac) ^ sw_a) << 4));
        bRel[kh] = (uint32_t)(br * 64 + (((2 * kh + bc) ^ sw_b) << 4));
    }
    const uint32_t aBase = (uint32_t)(m_off * 64);
    const uint32_t bBase = (uint32_t)(n_off * 64) + 2u * BF_TILE;

    #pragma unroll
    for (int i = 0; i < 2; i++)
        #pragma unroll
        for (int j = 0; j < 8; j++)
            #pragma unroll
            for (int k = 0; k < 4; k++) acc[i][j][k] = 0.f;

    stage(0, sb);
    cp_commit();
    stage(1, sb + BF_STAGE);
    cp_commit();

    for (int kc = 0; kc < KC; kc++) {
        cp_wait1();
        __syncthreads();
        if (kc + 2 < KC)
            stage(kc + 2, sb + ((kc + 2) % 3) * BF_STAGE);
        cp_commit();

        const uint32_t tA = sb + (kc % 3) * BF_STAGE;

        #pragma unroll
        for (int kh = 0; kh < 2; kh++) {
            uint32_t ah[2][4], al[2][4];
            #pragma unroll
            for (int mt = 0; mt < 2; mt++) {
                const uint32_t a_addr = tA + aBase + mt * 1024 + aRel[kh];
                ldsm_x4(ah[mt], a_addr);
                ldsm_x4(al[mt], a_addr + BF_TILE);
            }
            #pragma unroll
            for (int nt = 0; nt < 8; nt++) {
                const uint32_t b_addr = tA + bBase + nt * 512 + bRel[kh];
                uint32_t bh[2], bl[2];
                ldsm_x2(bh, b_addr);
                ldsm_x2(bl, b_addr + BF_TILE);
                #pragma unroll
                for (int mt = 0; mt < 2; mt++) {
                    mma16(acc[mt][nt], al[mt], bh);
                    mma16(acc[mt][nt], ah[mt], bl);
                    mma16(acc[mt][nt], ah[mt], bh);
                }
            }
        }
    }
    __syncthreads();
}

// ---------------------------------------------------------------------------
// tf32 1x pipelined GEMM (3 stages, ONE barrier per chunk).
//   A element (r,k): AM0: sA[r*36+k]  AM1: sA[k*132+r]
//   B element (k,n): BM0: sB[n*36+k]  BM1: sB[k*132+n]
// ---------------------------------------------------------------------------
template<int AM, int BM, class StageF>
__device__ __forceinline__ void gemm_tf(int KC, StageF stage, float (*acc)[8][4])
{
    extern __shared__ char dsm[];
    const uint32_t sb = (uint32_t)__cvta_generic_to_shared(dsm);
    const int tid  = threadIdx.x;
    const int lane = tid & 31;
    const int m_off = ((tid >> 5) & 3) * 32;
    const int n_off = (tid >> 7) * 64;
    const int gid = lane >> 2, tig = lane & 3;

    #pragma unroll
    for (int i = 0; i < 2; i++)
        #pragma unroll
        for (int j = 0; j < 8; j++)
            #pragma unroll
            for (int k = 0; k < 4; k++) acc[i][j][k] = 0.f;

    stage(0, sb, sb + TILE_B_OFF);
    cp_commit();
    stage(1, sb + STAGE_BYTES, sb + STAGE_BYTES + TILE_B_OFF);
    cp_commit();

    for (int kc = 0; kc < KC; kc++) {
        cp_wait1();
        __syncthreads();
        if (kc + 2 < KC) {
            const uint32_t nb = sb + ((kc + 2) % 3) * STAGE_BYTES;
            stage(kc + 2, nb, nb + TILE_B_OFF);
        }
        cp_commit();

        const int s = kc % 3;
        const float* sA = (const float*)(dsm + s * STAGE_BYTES);
        const float* sB = (const float*)(dsm + s * STAGE_BYTES + TILE_B_OFF);

        #pragma unroll
        for (int k8 = 0; k8 < 4; k8++) {
            const int kb = k8 * 8;
            uint32_t a[2][4];
            #pragma unroll
            for (int mt = 0; mt < 2; mt++) {
                const int r0 = m_off + mt * 16 + gid;
                if (AM == 0) {
                    a[mt][0] = f2tf(sA[r0 * 36 + kb + tig]);
                    a[mt][1] = f2tf(sA[(r0 + 8) * 36 + kb + tig]);
                    a[mt][2] = f2tf(sA[r0 * 36 + kb + tig + 4]);
                    a[mt][3] = f2tf(sA[(r0 + 8) * 36 + kb + tig + 4]);
                } else {
                    a[mt][0] = f2tf(sA[(kb + tig) * 132 + r0]);
                    a[mt][1] = f2tf(sA[(kb + tig) * 132 + r0 + 8]);
                    a[mt][2] = f2tf(sA[(kb + tig + 4) * 132 + r0]);
                    a[mt][3] = f2tf(sA[(kb + tig + 4) * 132 + r0 + 8]);
                }
            }
            #pragma unroll
            for (int nt = 0; nt < 8; nt++) {
                const int n = n_off + nt * 8 + gid;
                uint32_t bb[2];
                if (BM == 0) {
                    bb[0] = f2tf(sB[n * 36 + kb + tig]);
                    bb[1] = f2tf(sB[n * 36 + kb + tig + 4]);
                } else {
                    bb[0] = f2tf(sB[(kb + tig) * 132 + n]);
                    bb[1] = f2tf(sB[(kb + tig + 4) * 132 + n]);
                }
                #pragma unroll
                for (int mt = 0; mt < 2; mt++)
                    mma8(acc[mt][nt], a[mt], bb);
            }
        }
    }
    __syncthreads();
}

// ---------------------------------------------------------------------------
// Pre-split kernels
// ---------------------------------------------------------------------------
__global__ __launch_bounds__(256) void k_split_tr(const float* __restrict__ src,
                                                  uint32_t* __restrict__ hi,
                                                  uint32_t* __restrict__ lo)
{
    __shared__ float tile[32][33];
    const int b  = blockIdx.z;
    const int x0 = blockIdx.x * 32;   // t
    const int y0 = blockIdx.y * 32;   // d
    const int tid = threadIdx.x;
    const int li = tid & 31, lj = tid >> 5;
    #pragma unroll
    for (int j = lj; j < 32; j += 8)
        tile[j][li] = src[(size_t)b * ND * NT + (size_t)(y0 + j) * NT + x0 + li];
    __syncthreads();
    #pragma unroll
    for (int i = 0; i < 2; i++) {
        int id = tid + i * 256;
        int tt = id >> 4, w = id & 15;
        float e = tile[2 * w][tt], o = tile[2 * w + 1][tt];
        uint32_t h, l;
        bfsplit2(e, o, h, l);
        size_t off = ((size_t)b * NT + x0 + tt) * (ND / 2) + y0 / 2 + w;
        hi[off] = h;
        lo[off] = l;
    }
}

__global__ __launch_bounds__(256) void k_split_w(const float* __restrict__ src,
                                                 uint32_t* __restrict__ hi,
                                                 uint32_t* __restrict__ lo)
{
    const size_t w = (size_t)blockIdx.x * 256 + threadIdx.x;
    float2 v = ((const float2*)src)[w];
    uint32_t h, l;
    bfsplit2(v.x, v.y, h, l);
    hi[w] = h;
    lo[w] = l;
}

// gamma/beta transpose: src [NL, NT] -> dst [NT, NL]
__global__ void k_transpose(const float* __restrict__ src, float* __restrict__ dst)
{
    __shared__ float tile[32][33];
    const int x  = blockIdx.x * 32 + threadIdx.x;
    const int y0 = blockIdx.y * 32;
    #pragma unroll
    for (int j = threadIdx.y; j < 32; j += 8)
        tile[j][threadIdx.x] = src[(size_t)(y0 + j) * NT + x];
    __syncthreads();
    const int xo  = blockIdx.y * 32 + threadIdx.x;
    const int yo0 = blockIdx.x * 32;
    #pragma unroll
    for (int j = threadIdx.y; j < 32; j += 8)
        dst[(size_t)(yo0 + j) * NL + xo] = tile[threadIdx.x][j];
}

// ---------------------------------------------------------------------------
// GEMM kernels (all CTA 128x128, R9 config)
// ---------------------------------------------------------------------------

// Projection (bf16x3): C[b,t,l] = sum_d XT[b,t,d] * W[l,d] + bias[l]
// Output written as split hi/lo bf16 [b,t,l]. Grid: (NL/128, NT/128, NB)
__global__ __launch_bounds__(256, 2)
void k_proj_bf(const uint32_t* __restrict__ Wh, const uint32_t* __restrict__ Wl,
               const uint32_t* __restrict__ Xh, const uint32_t* __restrict__ Xl,
               const float* __restrict__ bias,
               uint32_t* __restrict__ Ch, uint32_t* __restrict__ Cl)
{
    const int b  = blockIdx.z;
    const int n0 = blockIdx.x * 128;   // l
    const int m0 = blockIdx.y * 128;   // t
    const uint32_t* XhB = Xh + ((size_t)b * NT + m0) * (ND / 2);
    const uint32_t* XlB = Xl + ((size_t)b * NT + m0) * (ND / 2);
    const uint32_t* WhB = Wh + (size_t)n0 * (ND / 2);
    const uint32_t* WlB = Wl + (size_t)n0 * (ND / 2);

    float acc[2][8][4];
    auto stage = [&](int kc, uint32_t base) {
        stage_bf(base,               XhB + kc * 16, ND / 2);
        stage_bf(base + BF_TILE,     XlB + kc * 16, ND / 2);
        stage_bf(base + 2 * BF_TILE, WhB + kc * 16, ND / 2);
        stage_bf(base + 3 * BF_TILE, WlB + kc * 16, ND / 2);
    };
    gemm_bf3(ND / 32, stage, acc);

    const int tid = threadIdx.x, lane = tid & 31;
    const int m_off = ((tid >> 5) & 3) * 32, n_off = (tid >> 7) * 64;
    const int gid = lane >> 2, tig = lane & 3;
    #pragma unroll
    for (int mt = 0; mt < 2; mt++) {
        const int r0 = m0 + m_off + mt * 16 + gid;
        #pragma unroll
        for (int nt = 0; nt < 8; nt++) {
            const int col = n0 + n_off + nt * 8 + tig * 2;
            float2 bi = *(const float2*)(bias + col);
            uint32_t h, l;
            size_t o0 = ((size_t)b * NT + r0) * (NL / 2) + col / 2;
            bfsplit2(acc[mt][nt][0] + bi.x, acc[mt][nt][1] + bi.y, h, l);
            Ch[o0] = h; Cl[o0] = l;
            size_t o1 = ((size_t)b * NT + r0 + 8) * (NL / 2) + col / 2;
            bfsplit2(acc[mt][nt][2] + bi.x, acc[mt][nt][3] + bi.y, h, l);
            Ch[o1] = h; Cl[o1] = l;
        }
    }
}

// Scores (bf16x3): S[b,t,s] = sum_l TH[b,t,l] * PH[b,s,l]. Grid (16,16,NB)
__global__ __launch_bounds__(256, 2)
void k_scores_bf(const uint32_t* __restrict__ Ah, const uint32_t* __restrict__ Al,
                 const uint32_t* __restrict__ Bh, const uint32_t* __restrict__ Bl,
                 float* __restrict__ S)
{
    const int b  = blockIdx.z;
    const int n0 = blockIdx.x * 128;   // s
    const int m0 = blockIdx.y * 128;   // t
    const uint32_t* AhB = Ah + ((size_t)b * NT + m0) * (NL / 2);
    const uint32_t* AlB = Al + ((size_t)b * NT + m0) * (NL / 2);
    const uint32_t* BhB = Bh + ((size_t)b * NT + n0) * (NL / 2);
    const uint32_t* BlB = Bl + ((size_t)b * NT + n0) * (NL / 2);

    float acc[2][8][4];
    auto stage = [&](int kc, uint32_t base) {
        stage_bf(base,               AhB + kc * 16, NL / 2);
        stage_bf(base + BF_TILE,     AlB + kc * 16, NL / 2);
        stage_bf(base + 2 * BF_TILE, BhB + kc * 16, NL / 2);
        stage_bf(base + 3 * BF_TILE, BlB + kc * 16, NL / 2);
    };
    gemm_bf3(NL / 32, stage, acc);

    const int tid = threadIdx.x, lane = tid & 31;
    const int m_off = ((tid >> 5) & 3) * 32, n_off = (tid >> 7) * 64;
    const int gid = lane >> 2, tig = lane & 3;
    float* Sb = S + (size_t)b * NT * NT;
    #pragma unroll
    for (int mt = 0; mt < 2; mt++) {
        const int r0 = m0 + m_off + mt * 16 + gid;
        #pragma unroll
        for (int nt = 0; nt < 8; nt++) {
            const int col = n0 + n_off + nt * 8 + tig * 2;
            *(float2*)(Sb + (size_t)r0 * NT + col) =
                make_float2(acc[mt][nt][0], acc[mt][nt][1]);
            *(float2*)(Sb + (size_t)(r0 + 8) * NT + col) =
                make_float2(acc[mt][nt][2], acc[mt][nt][3]);
        }
    }
}

// g-projection (tf32 1x): C[b,t,l] = sum_d X[b,d,t] * W[l,d] + bias[l]
// A = X (M=t, mode1), B = W (mode0). Grid: (NL/128, NT/128, NB)
__global__ __launch_bounds__(256, 2)
void k_proj_tf(const float* __restrict__ W, const float* __restrict__ X,
               const float* __restrict__ bias, float* __restrict__ C)
{
    const int b  = blockIdx.z;
    const int n0 = blockIdx.x * 128;   // l
    const int m0 = blockIdx.y * 128;   // t
    const float* Xb = X + (size_t)b * ND * NT;

    float acc[2][8][4];
    auto stage = [&](int kc, uint32_t bA, uint32_t bB) {
        stage_m1(bA, Xb + (size_t)(kc * 32) * NT + m0, NT);
        stage_m0(bB, W  + (size_t)n0 * ND + kc * 32, ND);
    };
    gemm_tf<1, 0>(ND / 32, stage, acc);

    const int tid = threadIdx.x, lane = tid & 31;
    const int m_off = ((tid >> 5) & 3) * 32, n_off = (tid >> 7) * 64;
    const int gid = lane >> 2, tig = lane & 3;
    float* Cb = C + (size_t)b * NT * NL;
    #pragma unroll
    for (int mt = 0; mt < 2; mt++) {
        const int r0 = m0 + m_off + mt * 16 + gid;
        #pragma unroll
        for (int nt = 0; nt < 8; nt++) {
            const int col = n0 + n_off + nt * 8 + tig * 2;
            float2 bi = *(const float2*)(bias + col);
            *(float2*)(Cb + (size_t)r0 * NL + col) =
                make_float2(acc[mt][nt][0] + bi.x, acc[mt][nt][1] + bi.y);
            *(float2*)(Cb + (size_t)(r0 + 8) * NL + col) =
                make_float2(acc[mt][nt][2] + bi.x, acc[mt][nt][3] + bi.y);
        }
    }
}

// t_x (tf32 1x): TX[b,t,l] = sum_s P[b,t,s] * GX[b,s,l].
// Emits per-CTA LN partials (deterministic). Grid (NL/128, NT/128, NB)
__global__ __launch_bounds__(256, 2)
void k_tx_tc(const float* __restrict__ P, const float* __restrict__ GX,
             float* __restrict__ TX)
{
    const int b  = blockIdx.z;
    const int n0 = blockIdx.x * 128;   // l
    const int m0 = blockIdx.y * 128;   // t
    const float* A  = P  + (size_t)b * NT * NT;
    const float* Bp = GX + (size_t)b * NT * NL;

    float acc[2][8][4];
    auto stage = [&](int kc, uint32_t bA, uint32_t bB) {
        stage_m0(bA, A  + (size_t)m0 * NT + kc * 32, NT);
        stage_m1(bB, Bp + (size_t)(kc * 32) * NL + n0, NL);
    };
    gemm_tf<0, 1>(NT / 32, stage, acc);

    const int tid = threadIdx.x, lane = tid & 31;
    const int m_off = ((tid >> 5) & 3) * 32, n_off = (tid >> 7) * 64;
    const int gid = lane >> 2, tig = lane & 3;
    float* Tb = TX + (size_t)b * NT * NL;
    float s = 0.f, q = 0.f;
    #pragma unroll
    for (int mt = 0; mt < 2; mt++) {
        const int r0 = m0 + m_off + mt * 16 + gid;
        #pragma unroll
        for (int nt = 0; nt < 8; nt++) {
            const int col = n0 + n_off + nt * 8 + tig * 2;
            float4 v = make_float4(acc[mt][nt][0], acc[mt][nt][1],
                                   acc[mt][nt][2], acc[mt][nt][3]);
            *(float2*)(Tb + (size_t)r0 * NL + col) = make_float2(v.x, v.y);
            *(float2*)(Tb + (size_t)(r0 + 8) * NL + col) = make_float2(v.z, v.w);
            s += v.x + v.y + v.z + v.w;
            q += v.x * v.x + v.y * v.y + v.z * v.z + v.w * v.w;
        }
    }
    // Deterministic per-CTA LN partials.
    extern __shared__ char dsm[];
    float* red = (float*)dsm;
    #pragma unroll
    for (int o = 16; o > 0; o >>= 1) {
        s += __shfl_xor_sync(0xffffffffu, s, o);
        q += __shfl_xor_sync(0xffffffffu, q, o);
    }
    __syncthreads();
    if (lane == 0) { red[tid >> 5] = s; red[8 + (tid >> 5)] = q; }
    __syncthreads();
    if (tid == 0) {
        float ts = 0.f, tq = 0.f;
        #pragma unroll
        for (int w = 0; w < 8; w++) { ts += red[w]; tq += red[8 + w]; }
        const int cta = blockIdx.y * 4 + blockIdx.x;   // 0..63 per batch
        g_part[(b * 64 + cta) * 2]     = ts;
        g_part[(b * 64 + cta) * 2 + 1] = tq;
    }
}

// Out (tf32 1x): Out[b,o,t] = sum_l OW[o,l] * H[b,t,l] + ob[o] + in2[b,o,t].
// Grid (NT/128, ND/128, NB)
__global__ __launch_bounds__(256, 2)
void k_out_tc(const float* __restrict__ OW, const float* __restrict__ H,
              const float* __restrict__ ob, const float* __restrict__ in2,
              float* __restrict__ Out)
{
    const int b  = blockIdx.z;
    const int n0 = blockIdx.x * 128;   // t
    const int m0 = blockIdx.y * 128;   // o
    const float* Hb = H + (size_t)b * NT * NL;

    float acc[2][8][4];
    auto stage = [&](int kc, uint32_t bA, uint32_t bB) {
        stage_m0(bA, OW + (size_t)m0 * NL + kc * 32, NL);
        stage_m0(bB, Hb + (size_t)n0 * NL + kc * 32, NL);
    };
    gemm_tf<0, 0>(NL / 32, stage, acc);

    const int tid = threadIdx.x, lane = tid & 31;
    const int m_off = ((tid >> 5) & 3) * 32, n_off = (tid >> 7) * 64;
    const int gid = lane >> 2, tig = lane & 3;
    #pragma unroll
    for (int mt = 0; mt < 2; mt++) {
        const int r0 = m0 + m_off + mt * 16 + gid;
        const float bi0 = ob[r0], bi1 = ob[r0 + 8];
        const size_t base0 = ((size_t)b * ND + r0) * NT;
        const size_t base1 = ((size_t)b * ND + r0 + 8) * NT;
        #pragma unroll
        for (int nt = 0; nt < 8; nt++) {
            const int col = n0 + n_off + nt * 8 + tig * 2;
            float2 q0 = *(const float2*)(in2 + base0 + col);
            float2 q1 = *(const float2*)(in2 + base1 + col);
            *(float2*)(Out + base0 + col) =
                make_float2(acc[mt][nt][0] + bi0 + q0.x, acc[mt][nt][1] + bi0 + q0.y);
            *(float2*)(Out + base1 + col) =
                make_float2(acc[mt][nt][2] + bi1 + q1.x, acc[mt][nt][3] + bi1 + q1.y);
        }
    }
}

// ---------------------------------------------------------------------------
// Elementwise / reductions
// ---------------------------------------------------------------------------
__device__ __forceinline__ float warpMax(float v) {
    #pragma unroll
    for (int o = 16; o > 0; o >>= 1) v = fmaxf(v, __shfl_xor_sync(0xffffffffu, v, o));
    return v;
}
__device__ __forceinline__ float warpSum(float v) {
    #pragma unroll
    for (int o = 16; o > 0; o >>= 1) v += __shfl_xor_sync(0xffffffffu, v, o);
    return v;
}

__global__ __launch_bounds__(256) void k_softmax(float* __restrict__ S)
{
    float* p = S + (size_t)blockIdx.x * NT;
    const int tid = threadIdx.x;
    float4 v0 = ((float4*)p)[tid];
    float4 v1 = ((float4*)p)[tid + 256];

    __shared__ float sm[8];
    float m = fmaxf(fmaxf(fmaxf(v0.x, v0.y), fmaxf(v0.z, v0.w)),
                    fmaxf(fmaxf(v1.x, v1.y), fmaxf(v1.z, v1.w)));
    m = warpMax(m);
    if ((tid & 31) == 0) sm[tid >> 5] = m;
    __syncthreads();
    if (tid < 32) {
        float t = (tid < 8) ? sm[tid] : -1e30f;
        t = warpMax(t);
        if (tid == 0) sm[0] = t;
    }
    __syncthreads();
    const float bm = sm[0];
    __syncthreads();

    v0.x = __expf(v0.x - bm); v0.y = __expf(v0.y - bm);
    v0.z = __expf(v0.z - bm); v0.w = __expf(v0.w - bm);
    v1.x = __expf(v1.x - bm); v1.y = __expf(v1.y - bm);
    v1.z = __expf(v1.z - bm); v1.w = __expf(v1.w - bm);
    float s = v0.x + v0.y + v0.z + v0.w + v1.x + v1.y + v1.z + v1.w;
    s = warpSum(s);
    if ((tid & 31) == 0) sm[tid >> 5] = s;
    __syncthreads();
    if (tid < 32) {
        float t = (tid < 8) ? sm[tid] : 0.f;
        t = warpSum(t);
        if (tid == 0) sm[0] = t;
    }
    __syncthreads();
    const float inv = 1.f / sm[0];
    v0.x *= inv; v0.y *= inv; v0.z *= inv; v0.w *= inv;
    v1.x *= inv; v1.y *= inv; v1.z *= inv; v1.w *= inv;
    ((float4*)p)[tid] = v0;
    ((float4*)p)[tid + 256] = v1;
}

__global__ void k_finalize()
{
    const int b = threadIdx.x;
    if (b >= NB) return;
    float s = 0.f, q = 0.f;
    for (int c = 0; c < 64; c++) {
        s += g_part[(b * 64 + c) * 2];
        q += g_part[(b * 64 + c) * 2 + 1];
    }
    const float n = (float)NL * (float)NT;
    const float mean = s / n;
    const float var  = q / n - mean * mean;
    g_stats[2 * b]     = mean;
    g_stats[2 * b + 1] = rsqrtf(var + 1e-5f);
}

// H = relu((TX - mu) * rstd * G2 + B2), all [b,t,l]
__global__ __launch_bounds__(256) void k_ln(const float* __restrict__ TX,
                                            const float* __restrict__ G2,
                                            const float* __restrict__ B2,
                                            float* __restrict__ H)
{
    const int b = blockIdx.y;
    const size_t i = (size_t)blockIdx.x * 256 + threadIdx.x;
    const float mu = g_stats[2 * b], rs = g_stats[2 * b + 1];
    float4 x  = ((const float4*)(TX + (size_t)b * NL * NT))[i];
    float4 g  = ((const float4*)G2)[i];
    float4 be = ((const float4*)B2)[i];
    float4 h;
    h.x = fmaxf((x.x - mu) * rs * g.x + be.x, 0.f);
    h.y = fmaxf((x.y - mu) * rs * g.y + be.y, 0.f);
    h.z = fmaxf((x.z - mu) * rs * g.z + be.z, 0.f);
    h.w = fmaxf((x.w - mu) * rs * g.w + be.w, 0.f);
    ((float4*)(H + (size_t)b * NL * NT))[i] = h;
}

// ---------------------------------------------------------------------------
// Launch
// ---------------------------------------------------------------------------
extern "C" void kernel_launch(void* const* d_in, const int* in_sizes, int n_in,
                              void* d_out, int out_size)
{
    const float* input1  = (const float*)d_in[0];
    const float* input2  = (const float*)d_in[1];
    const float* theta_w = (const float*)d_in[2];
    const float* theta_b = (const float*)d_in[3];
    const float* phi_w   = (const float*)d_in[4];
    const float* phi_b   = (const float*)d_in[5];
    const float* g_w     = (const float*)d_in[6];
    const float* g_b     = (const float*)d_in[7];
    const float* ln_g    = (const float*)d_in[8];
    const float* ln_b    = (const float*)d_in[9];
    const float* out_w   = (const float*)d_in[10];
    const float* out_b   = (const float*)d_in[11];
    float* out = (float*)d_out;

    uint32_t *X1h, *X1l, *X2h, *X2l, *TWh, *TWl, *PWh, *PWl;
    uint32_t *THh, *THl, *PHh, *PHl;
    float *GX, *TX, *H, *S, *G2, *B2;
    cudaGetSymbolAddress((void**)&X1h, g_X1h);
    cudaGetSymbolAddress((void**)&X1l, g_X1l);
    cudaGetSymbolAddress((void**)&X2h, g_X2h);
    cudaGetSymbolAddress((void**)&X2l, g_X2l);
    cudaGetSymbolAddress((void**)&TWh, g_TWh);
    cudaGetSymbolAddress((void**)&TWl, g_TWl);
    cudaGetSymbolAddress((void**)&PWh, g_PWh);
    cudaGetSymbolAddress((void**)&PWl, g_PWl);
    cudaGetSymbolAddress((void**)&THh, g_THh);
    cudaGetSymbolAddress((void**)&THl, g_THl);
    cudaGetSymbolAddress((void**)&PHh, g_PHh);
    cudaGetSymbolAddress((void**)&PHl, g_PHl);
    cudaGetSymbolAddress((void**)&GX, g_GX);
    cudaGetSymbolAddress((void**)&TX, g_TX);
    cudaGetSymbolAddress((void**)&H,  g_H);
    cudaGetSymbolAddress((void**)&S,  g_S);
    cudaGetSymbolAddress((void**)&G2, g_G2);
    cudaGetSymbolAddress((void**)&B2, g_B2);

    cudaFuncSetAttribute(k_proj_bf,   cudaFuncAttributeMaxDynamicSharedMemorySize, SMEMB_BF);
    cudaFuncSetAttribute(k_scores_bf, cudaFuncAttributeMaxDynamicSharedMemorySize, SMEMB_BF);
    cudaFuncSetAttribute(k_proj_tf,   cudaFuncAttributeMaxDynamicSharedMemorySize, SMEMB_TF);
    cudaFuncSetAttribute(k_tx_tc,     cudaFuncAttributeMaxDynamicSharedMemorySize, SMEMB_TF);
    cudaFuncSetAttribute(k_out_tc,    cudaFuncAttributeMaxDynamicSharedMemorySize, SMEMB_TF);

    dim3 blk(256);

    // Pre-splits
    dim3 gst(NT / 32, ND / 32, NB);
    k_split_tr<<<gst, blk>>>(input2, X2h, X2l);
    k_split_tr<<<gst, blk>>>(input1, X1h, X1l);
    k_split_w<<<NL * ND / 512, blk>>>(theta_w, TWh, TWl);
    k_split_w<<<NL * ND / 512, blk>>>(phi_w, PWh, PWl);

    dim3 gtr(NT / 32, NL / 32);
    k_transpose<<<gtr, dim3(32, 8)>>>(ln_g, G2);
    k_transpose<<<gtr, dim3(32, 8)>>>(ln_b, B2);

    // Projections
    dim3 gproj(NL / 128, NT / 128, NB);
    k_proj_bf<<<gproj, blk, SMEMB_BF>>>(TWh, TWl, X2h, X2l, theta_b, THh, THl);
    k_proj_bf<<<gproj, blk, SMEMB_BF>>>(PWh, PWl, X1h, X1l, phi_b, PHh, PHl);
    k_proj_tf<<<gproj, blk, SMEMB_TF>>>(g_w, input1, g_b, GX);

    // Scores + softmax
    dim3 gsc(NT / 128, NT / 128, NB);
    k_scores_bf<<<gsc, blk, SMEMB_BF>>>(THh, THl, PHh, PHl, S);
    k_softmax<<<NB * NT, 256>>>(S);

    // Attention apply (+ fused LN partials)
    dim3 gtx(NL / 128, NT / 128, NB);
    k_tx_tc<<<gtx, blk, SMEMB_TF>>>(S, GX, TX);

    // LayerNorm
    k_finalize<<<1, NB>>>();
    k_ln<<<dim3(NL * NT / 1024, NB), 256>>>(TX, G2, B2, H);

    // Output GEMM
    dim3 gout(NT / 128, ND / 128, NB);
    k_out_tc<<<gout, blk, SMEMB_TF>>>(out_w, H, out_b, input2, out);
}